// round 6
// baseline (speedup 1.0000x reference)
#include <cuda_runtime.h>

typedef unsigned long long ULL;

#define NB  2
#define SEQ 512
#define HD  256

// Scratch (allocation-free):
//   g_dproj[b][q][d]  = w[d]*(dec_proj + bm[d])
//   g_eprojT[b][d][e] = w[d]*enc_proj
//   g_usum[b][q] = sum_d g_dproj,  g_vsum[b][e] = sum_d g_eprojT
__device__ float g_dproj[NB*SEQ*HD];
__device__ float g_eprojT[NB*HD*SEQ];
__device__ float g_usum[NB*SEQ];
__device__ float g_vsum[NB*SEQ];

__device__ __forceinline__ ULL add2(ULL a, ULL b) {
    ULL r; asm("add.rn.f32x2 %0,%1,%2;" : "=l"(r) : "l"(a), "l"(b)); return r;
}
__device__ __forceinline__ ULL fma2(ULL a, ULL b, ULL c) {
    ULL r; asm("fma.rn.f32x2 %0,%1,%2,%3;" : "=l"(r) : "l"(a), "l"(b), "l"(c)); return r;
}
__device__ __forceinline__ float f_lo(ULL a) { return __uint_as_float((unsigned)a); }
__device__ __forceinline__ float f_hi(ULL a) { return __uint_as_float((unsigned)(a >> 32)); }

// ---------------------------------------------------------------------------
// Zero kernel: clears out (atomic accumulation target) and the sum buffers.
// ---------------------------------------------------------------------------
__global__ __launch_bounds__(256) void zero_kernel(float4* __restrict__ out)
{
    int gid = blockIdx.x*256 + threadIdx.x;        // 512*256 = 131072 float4 = 524288 f
    out[gid] = make_float4(0.f, 0.f, 0.f, 0.f);
    if (gid < NB*SEQ) { g_usum[gid] = 0.f; g_vsum[gid] = 0.f; }
}

// ---------------------------------------------------------------------------
// Fused projection kernel: C = A * B^T (64x64 tile, K=256), f32x2-packed k.
// blockIdx.z: 0,1 = dec (b=0,1) -> g_dproj   (+ usum partials)
//             2,3 = enc (b=0,1) -> g_eprojT  (+ vsum partials)
// ---------------------------------------------------------------------------
__global__ __launch_bounds__(256) void proj_kernel(
    const float* __restrict__ dec, const float* __restrict__ enc,
    const float* __restrict__ Wm,  const float* __restrict__ bm,
    const float* __restrict__ wo)
{
    __shared__ __align__(16) ULL AsP[64*17];   // k-pairs, row stride 17 (8B units)
    __shared__ __align__(16) ULL BsP[64*17];

    const int tx = threadIdx.x, ty = threadIdx.y;
    const int t  = ty*16 + tx;
    const int typ = blockIdx.z >> 1;
    const int b   = blockIdx.z & 1;

    const float *Ap, *Bp;
    float* Cp;
    int lda, ldb, ldc, row0, col0;
    if (typ == 0) {                       // dec_proj: rows=q (512), cols=d (256)
        row0 = blockIdx.x * 64; col0 = blockIdx.y * 64;
        Ap = dec + (size_t)b*SEQ*HD + (size_t)row0*HD;  lda = HD;
        Bp = Wm + HD + (size_t)col0*(2*HD);             ldb = 2*HD;   // Wd rows
        Cp = g_dproj + (size_t)b*SEQ*HD;                ldc = HD;
    } else {                              // enc_projT: rows=d (256), cols=e (512)
        row0 = blockIdx.y * 64; col0 = blockIdx.x * 64;
        Ap = Wm + (size_t)row0*(2*HD);                  lda = 2*HD;   // We rows
        Bp = enc + (size_t)b*SEQ*HD + (size_t)col0*HD;  ldb = HD;
        Cp = g_eprojT + (size_t)b*HD*SEQ;               ldc = SEQ;
    }

    ULL acc[4][4];
    #pragma unroll
    for (int i=0;i<4;i++)
        #pragma unroll
        for (int j=0;j<4;j++) acc[i][j]=0ULL;

    for (int c = 0; c < 8; c++) {
        __syncthreads();
        #pragma unroll
        for (int r = 0; r < 2; r++) {
            int f4 = t + r*256;
            int i  = f4 >> 3, kg = f4 & 7;     // kg: float4 index within 32-k chunk
            float4 av = *(const float4*)(Ap + (size_t)i*lda + c*32 + kg*4);
            float4 bv = *(const float4*)(Bp + (size_t)i*ldb + c*32 + kg*4);
            float2* pa = (float2*)&AsP[i*17 + kg*2];
            pa[0] = make_float2(av.x, av.y);
            pa[1] = make_float2(av.z, av.w);
            float2* pb = (float2*)&BsP[i*17 + kg*2];
            pb[0] = make_float2(bv.x, bv.y);
            pb[1] = make_float2(bv.z, bv.w);
        }
        __syncthreads();
        #pragma unroll 8
        for (int kk = 0; kk < 16; kk++) {      // 16 k-pairs = 32 k
            ULL a2[4], b2[4];
            #pragma unroll
            for (int i=0;i<4;i++) a2[i] = AsP[(4*ty+i)*17 + kk];
            #pragma unroll
            for (int j=0;j<4;j++) b2[j] = BsP[(4*tx+j)*17 + kk];
            #pragma unroll
            for (int i=0;i<4;i++)
                #pragma unroll
                for (int j=0;j<4;j++)
                    acc[i][j] = fma2(a2[i], b2[j], acc[i][j]);
        }
    }

    if (typ == 0) {
        const int d0 = col0 + 4*tx;
        float w4[4], bm4[4];
        #pragma unroll
        for (int j=0;j<4;j++){ w4[j] = wo[d0+j]; bm4[j] = bm[d0+j]; }
        #pragma unroll
        for (int i=0;i<4;i++) {
            int q = row0 + 4*ty + i;
            float s[4];
            #pragma unroll
            for (int j=0;j<4;j++)
                s[j] = (f_lo(acc[i][j]) + f_hi(acc[i][j]) + bm4[j]) * w4[j];
            *(float4*)(Cp + (size_t)q*ldc + d0) = make_float4(s[0],s[1],s[2],s[3]);
            // usum partial: sum over this thread's 4 d, then over the 16 tx lanes
            float loc = (s[0]+s[1]) + (s[2]+s[3]);
            loc += __shfl_xor_sync(0xFFFFFFFFu, loc, 1);
            loc += __shfl_xor_sync(0xFFFFFFFFu, loc, 2);
            loc += __shfl_xor_sync(0xFFFFFFFFu, loc, 4);
            loc += __shfl_xor_sync(0xFFFFFFFFu, loc, 8);
            if (tx == 0) atomicAdd(&g_usum[b*SEQ + q], loc);
        }
    } else {
        float vv[4][4];
        #pragma unroll
        for (int i=0;i<4;i++) {
            int d = row0 + 4*ty + i;
            float w = wo[d];
            #pragma unroll
            for (int j=0;j<4;j++)
                vv[i][j] = (f_lo(acc[i][j]) + f_hi(acc[i][j])) * w;
            *(float4*)(Cp + (size_t)d*ldc + col0 + 4*tx) =
                make_float4(vv[i][0],vv[i][1],vv[i][2],vv[i][3]);
        }
        #pragma unroll
        for (int j=0;j<4;j++) {
            float loc = (vv[0][j]+vv[1][j]) + (vv[2][j]+vv[3][j]);
            atomicAdd(&g_vsum[b*SEQ + col0 + 4*tx + j], loc);
        }
    }
}

// ---------------------------------------------------------------------------
// Main pairwise kernel, d-split by 2 for occupancy.
// out[b,q,e] += Σ_{d in half} 0.5*sgn(w)*|u+v|   (+ 0.5*(Σu+Σv) + bo on half 0)
// Packed f32x2 over pairs of adjacent e.  64q x 64e per block, 4x4 per thread.
// ---------------------------------------------------------------------------
__global__ __launch_bounds__(256) void attn_kernel(
    const float* __restrict__ wo, const float* __restrict__ bo,
    float* __restrict__ out)
{
    __shared__ __align__(16) float Dd[64*66];   // u duplicated: [q][2*hh+p]
    __shared__ __align__(16) float Es[32*68];   // v: [hh][e]
    __shared__ __align__(16) float Sg[256];     // 0.5*sgn(w) duplicated, this d-half

    const int tx = threadIdx.x, ty = threadIdx.y;
    const int t  = ty*16 + tx;
    const int et = blockIdx.x, qt = blockIdx.y;
    const int b  = blockIdx.z >> 1, dh = blockIdx.z & 1;

    const float* U = g_dproj  + (size_t)b*SEQ*HD + (size_t)qt*64*HD + dh*128;
    const float* V = g_eprojT + (size_t)b*HD*SEQ + (size_t)dh*128*SEQ + et*64;

    if (t < 128) {
        float w = wo[dh*128 + t];
        float sg = (w > 0.f) ? 0.5f : ((w < 0.f) ? -0.5f : 0.f);
        Sg[2*t] = sg; Sg[2*t+1] = sg;
    }

    ULL acc[4][2];
    #pragma unroll
    for (int i=0;i<4;i++){ acc[i][0]=0ULL; acc[i][1]=0ULL; }

    for (int c = 0; c < 4; c++) {               // 4 chunks x 32 d = 128 d
        __syncthreads();
        #pragma unroll
        for (int r = 0; r < 2; r++) {           // stage u (duplicated pairs)
            int f4 = t + r*256;
            int q = f4 >> 3, hg = f4 & 7;
            float4 dv = *(const float4*)(U + (size_t)q*HD + c*32 + hg*4);
            float2* p = (float2*)&Dd[q*66 + hg*8];
            p[0] = make_float2(dv.x, dv.x);
            p[1] = make_float2(dv.y, dv.y);
            p[2] = make_float2(dv.z, dv.z);
            p[3] = make_float2(dv.w, dv.w);
        }
        #pragma unroll
        for (int r = 0; r < 2; r++) {           // stage v
            int f4 = t + r*256;
            int h = f4 >> 4, eg = f4 & 15;
            *(float4*)&Es[h*68 + eg*4] =
                *(const float4*)(V + (size_t)(c*32 + h)*SEQ + eg*4);
        }
        __syncthreads();

        #pragma unroll 8
        for (int hh = 0; hh < 32; hh++) {
            ULL sg2 = *(const ULL*)&Sg[(c*32 + hh)*2];
            ULL u2[4], v2[2];
            #pragma unroll
            for (int i=0;i<4;i++) u2[i] = *(const ULL*)&Dd[(4*ty+i)*66 + 2*hh];
            v2[0] = *(const ULL*)&Es[hh*68 + 4*tx];
            v2[1] = *(const ULL*)&Es[hh*68 + 4*tx + 2];
            #pragma unroll
            for (int i=0;i<4;i++) {
                #pragma unroll
                for (int j=0;j<2;j++) {
                    ULL s2 = add2(u2[i], v2[j]);
                    s2 &= 0x7FFFFFFF7FFFFFFFULL;      // packed |s|
                    acc[i][j] = fma2(s2, sg2, acc[i][j]);
                }
            }
        }
    }

    const int q0 = qt*64 + 4*ty;
    const int e0 = et*64 + 4*tx;
    float* O = out + ((size_t)b*SEQ + q0)*SEQ + e0;

    float corr[4] = {0.f,0.f,0.f,0.f};          // per-e correction (half 0 only)
    float us[4]   = {0.f,0.f,0.f,0.f};
    if (dh == 0) {
        const float bov = bo[0];
        #pragma unroll
        for (int j=0;j<4;j++) corr[j] = 0.5f*g_vsum[b*SEQ + e0 + j] + bov;
        #pragma unroll
        for (int i=0;i<4;i++) us[i] = 0.5f*g_usum[b*SEQ + q0 + i];
    }
    #pragma unroll
    for (int i=0;i<4;i++) {
        atomicAdd(&O[(size_t)i*SEQ + 0], f_lo(acc[i][0]) + us[i] + corr[0]);
        atomicAdd(&O[(size_t)i*SEQ + 1], f_hi(acc[i][0]) + us[i] + corr[1]);
        atomicAdd(&O[(size_t)i*SEQ + 2], f_lo(acc[i][1]) + us[i] + corr[2]);
        atomicAdd(&O[(size_t)i*SEQ + 3], f_hi(acc[i][1]) + us[i] + corr[3]);
    }
}

extern "C" void kernel_launch(void* const* d_in, const int* in_sizes, int n_in,
                              void* d_out, int out_size)
{
    const float* dec = (const float*)d_in[0];
    const float* enc = (const float*)d_in[1];
    const float* Wm  = (const float*)d_in[2];
    const float* bm  = (const float*)d_in[3];
    const float* wo  = (const float*)d_in[4];
    const float* bo  = (const float*)d_in[5];
    float* out = (float*)d_out;

    zero_kernel<<<512, 256>>>((float4*)out);
    proj_kernel<<<dim3(8,4,4), dim3(16,16)>>>(dec, enc, Wm, bm, wo);
    attn_kernel<<<dim3(8,8,4), dim3(16,16)>>>(wo, bo, out);
}

// round 10
// speedup vs baseline: 1.1613x; 1.1613x over previous
#include <cuda_runtime.h>

typedef unsigned long long ULL;

#define NB  2
#define SEQ 512
#define HD  256

// Scratch (allocation-free):
//   g_dproj[b][q][d]  = w[d]*(dec_proj + bm[d])
//   g_eprojT[b][d][e] = w[d]*enc_proj
__device__ float g_dproj[NB*SEQ*HD];
__device__ float g_eprojT[NB*HD*SEQ];

__device__ __forceinline__ ULL add2(ULL a, ULL b) {
    ULL r; asm("add.rn.f32x2 %0,%1,%2;" : "=l"(r) : "l"(a), "l"(b)); return r;
}
__device__ __forceinline__ ULL fma2(ULL a, ULL b, ULL c) {
    ULL r; asm("fma.rn.f32x2 %0,%1,%2,%3;" : "=l"(r) : "l"(a), "l"(b), "l"(c)); return r;
}
__device__ __forceinline__ float f_lo(ULL a) { return __uint_as_float((unsigned)a); }
__device__ __forceinline__ float f_hi(ULL a) { return __uint_as_float((unsigned)(a >> 32)); }

// ---------------------------------------------------------------------------
// Projection kernel: C = A * B^T, k-pair packed, 32x64 tile, 256 thr,
// per-thread 4 rows x 2 cols.  Grid (64,1,4).
// z: 0,1 = dec (b=0,1) -> g_dproj ; 2,3 = enc (b=0,1) -> g_eprojT
// ---------------------------------------------------------------------------
__global__ __launch_bounds__(256) void proj_kernel(
    const float* __restrict__ dec, const float* __restrict__ enc,
    const float* __restrict__ Wm,  const float* __restrict__ bm,
    const float* __restrict__ wo)
{
    __shared__ __align__(16) ULL AsP[32*17];   // [row][kpair], stride 17
    __shared__ __align__(16) ULL BsP[16*66];   // [kpair][col], stride 66

    const int tx = threadIdx.x;                // 0..31
    const int ty = threadIdx.y;                // 0..7
    const int t  = ty*32 + tx;
    const int typ = blockIdx.z >> 1;
    const int b   = blockIdx.z & 1;
    const int bx  = blockIdx.x;

    int row0, col0;
    const float *Ap, *Bp;
    float* Cp;
    int lda, ldb, ldc;
    if (typ == 0) {                            // dec: rows=q (16 tiles), cols=d (4 tiles)
        row0 = (bx >> 2) * 32; col0 = (bx & 3) * 64;
        Ap = dec + (size_t)b*SEQ*HD + (size_t)row0*HD;  lda = HD;
        Bp = Wm + HD + (size_t)col0*(2*HD);             ldb = 2*HD;   // Wd rows
        Cp = g_dproj + (size_t)b*SEQ*HD;                ldc = HD;
    } else {                                   // enc: rows=d (8 tiles), cols=e (8 tiles)
        row0 = (bx >> 3) * 32; col0 = (bx & 7) * 64;
        Ap = Wm + (size_t)row0*(2*HD);                  lda = 2*HD;   // We rows
        Bp = enc + (size_t)b*SEQ*HD + (size_t)col0*HD;  ldb = HD;
        Cp = g_eprojT + (size_t)b*HD*SEQ;               ldc = SEQ;
    }

    ULL acc[4][2];
    #pragma unroll
    for (int i=0;i<4;i++){ acc[i][0]=0ULL; acc[i][1]=0ULL; }

    const int ar = t >> 3, akg = t & 7;        // A: 32 rows x 8 f4-groups

    for (int c = 0; c < 8; c++) {
        __syncthreads();
        {   // stage A (k-pairs, natural order)
            float4 av = *(const float4*)(Ap + (size_t)ar*lda + c*32 + akg*4);
            float2* pa = (float2*)&AsP[ar*17 + akg*2];
            pa[0] = make_float2(av.x, av.y);
            pa[1] = make_float2(av.z, av.w);
        }
        #pragma unroll
        for (int r = 0; r < 2; r++) {          // stage B transposed to [kpair][col]
            int f4i = t + r*256;
            int bc = f4i >> 3, bkg = f4i & 7;
            float4 bv = *(const float4*)(Bp + (size_t)bc*ldb + c*32 + bkg*4);
            *(float2*)&BsP[(bkg*2+0)*66 + bc] = make_float2(bv.x, bv.y);
            *(float2*)&BsP[(bkg*2+1)*66 + bc] = make_float2(bv.z, bv.w);
        }
        __syncthreads();
        #pragma unroll
        for (int kk = 0; kk < 16; kk++) {
            ULL a2[4];
            #pragma unroll
            for (int i=0;i<4;i++) a2[i] = AsP[(4*ty+i)*17 + kk];
            ulonglong2 b2 = *(const ulonglong2*)&BsP[kk*66 + 2*tx];  // LDS.128
            #pragma unroll
            for (int i=0;i<4;i++){
                acc[i][0] = fma2(a2[i], b2.x, acc[i][0]);
                acc[i][1] = fma2(a2[i], b2.y, acc[i][1]);
            }
        }
    }

    if (typ == 0) {
        const int d0 = col0 + 2*tx;
        const float w0 = wo[d0], w1 = wo[d0+1];
        const float m0 = bm[d0], m1 = bm[d0+1];
        #pragma unroll
        for (int i=0;i<4;i++) {
            int q = row0 + 4*ty + i;
            float sx = f_lo(acc[i][0]) + f_hi(acc[i][0]);
            float sy = f_lo(acc[i][1]) + f_hi(acc[i][1]);
            *(float2*)(Cp + (size_t)q*ldc + d0) =
                make_float2((sx + m0)*w0, (sy + m1)*w1);
        }
    } else {
        const int e0 = col0 + 2*tx;
        #pragma unroll
        for (int i=0;i<4;i++) {
            int d = row0 + 4*ty + i;
            float w = wo[d];
            float sx = f_lo(acc[i][0]) + f_hi(acc[i][0]);
            float sy = f_lo(acc[i][1]) + f_hi(acc[i][1]);
            *(float2*)(Cp + (size_t)d*ldc + e0) = make_float2(sx*w, sy*w);
        }
    }
}

// ---------------------------------------------------------------------------
// Main pairwise kernel: 32q x 64e tile, 256 thr, per-thread 4q x 1 e-pair,
// full d=256 per CTA.  Grid (8,16,2) = 256 CTAs = 2048 warps.
// out[b,q,e] = sum_d 0.5*sgn(w)|u+v| + 0.5*(Su[q]+Sv[e]) + bo
// Su/Sv accumulated during tile staging (each (q,d)/(d,e) loaded exactly once).
// ---------------------------------------------------------------------------
__global__ __launch_bounds__(256) void attn_kernel(
    const float* __restrict__ wo, const float* __restrict__ bo,
    float* __restrict__ out)
{
    __shared__ __align__(16) float Dd[32*66];   // u duplicated pairs: [q][2*hh+p]
    __shared__ __align__(16) float Es[32*68];   // v: [hh][e]
    __shared__ __align__(16) float Sg[512];     // 0.5*sgn(w) duplicated
    __shared__ float Usum[32];
    __shared__ __align__(16) float Vsum[64];

    const int tx = threadIdx.x;                 // 0..31 (e-pair)
    const int ty = threadIdx.y;                 // 0..7
    const int t  = ty*32 + tx;
    const int et = blockIdx.x, qt = blockIdx.y, b = blockIdx.z;

    const float* U = g_dproj  + (size_t)b*SEQ*HD + (size_t)qt*32*HD;
    const float* V = g_eprojT + (size_t)b*HD*SEQ + et*64;

    {
        float w = wo[t];
        float sg = (w > 0.f) ? 0.5f : ((w < 0.f) ? -0.5f : 0.f);
        Sg[2*t] = sg; Sg[2*t+1] = sg;
    }

    const int uq = t >> 3, uhg = t & 7;         // U staging: 32 q x 8 f4
    const int veg = t & 15, vh0 = t >> 4;       // V staging: rows vh0, vh0+16

    float  us_part = 0.f;
    float4 vp = make_float4(0.f,0.f,0.f,0.f);

    ULL acc[4] = {0ULL,0ULL,0ULL,0ULL};

    for (int c = 0; c < 8; c++) {
        __syncthreads();
        {   // stage U (duplicate pairs) + row-sum partial
            float4 av = *(const float4*)(U + (size_t)uq*HD + c*32 + uhg*4);
            us_part += (av.x + av.y) + (av.z + av.w);
            float2* p = (float2*)&Dd[uq*66 + uhg*8];
            p[0] = make_float2(av.x, av.x);
            p[1] = make_float2(av.y, av.y);
            p[2] = make_float2(av.z, av.z);
            p[3] = make_float2(av.w, av.w);
        }
        #pragma unroll
        for (int r = 0; r < 2; r++) {           // stage V + col-sum partial
            int h = vh0 + r*16;
            float4 bv = *(const float4*)(V + (size_t)(c*32 + h)*SEQ + veg*4);
            vp.x += bv.x; vp.y += bv.y; vp.z += bv.z; vp.w += bv.w;
            *(float4*)&Es[h*68 + veg*4] = bv;
        }
        __syncthreads();

        #pragma unroll 8
        for (int hh = 0; hh < 32; hh++) {
            ULL sg2 = *(const ULL*)&Sg[(c*32 + hh)*2];
            ULL v2  = *(const ULL*)&Es[hh*68 + 2*tx];
            #pragma unroll
            for (int i=0;i<4;i++) {
                ULL u2 = *(const ULL*)&Dd[(4*ty+i)*66 + 2*hh];
                ULL s2 = add2(u2, v2) & 0x7FFFFFFF7FFFFFFFULL;   // packed |u+v|
                acc[i] = fma2(s2, sg2, acc[i]);
            }
        }
    }

    // ---- Usum: reduce over the 8 hg-lanes sharing each q (consecutive lanes)
    us_part += __shfl_xor_sync(0xFFFFFFFFu, us_part, 1);
    us_part += __shfl_xor_sync(0xFFFFFFFFu, us_part, 2);
    us_part += __shfl_xor_sync(0xFFFFFFFFu, us_part, 4);
    if (uhg == 0) Usum[uq] = us_part;

    // ---- Vsum: partials to smem (reuse Dd), then 64-thread reduce
    __syncthreads();                            // done reading Dd/Es
    ((float4*)Dd)[vh0*16 + veg] = vp;
    __syncthreads();
    if (t < 64) {
        int eg = t >> 2, comp = t & 3;
        float s = 0.f;
        #pragma unroll
        for (int k = 0; k < 16; k++)
            s += ((const float*)Dd)[(k*16 + eg)*4 + comp];
        Vsum[t] = s;
    }
    __syncthreads();

    const float bov = bo[0];
    const int q0 = qt*32 + 4*ty;
    const int e0 = et*64 + 2*tx;
    const float cx = 0.5f*Vsum[2*tx]   + bov;
    const float cy = 0.5f*Vsum[2*tx+1] + bov;
    float* O = out + ((size_t)b*SEQ + q0)*SEQ + e0;
    #pragma unroll
    for (int i=0;i<4;i++) {
        float ui = 0.5f*Usum[4*ty + i];
        *(float2*)(O + (size_t)i*SEQ) =
            make_float2(f_lo(acc[i]) + ui + cx, f_hi(acc[i]) + ui + cy);
    }
}

extern "C" void kernel_launch(void* const* d_in, const int* in_sizes, int n_in,
                              void* d_out, int out_size)
{
    const float* dec = (const float*)d_in[0];
    const float* enc = (const float*)d_in[1];
    const float* Wm  = (const float*)d_in[2];
    const float* bm  = (const float*)d_in[3];
    const float* wo  = (const float*)d_in[4];
    const float* bo  = (const float*)d_in[5];
    float* out = (float*)d_out;

    proj_kernel<<<dim3(64,1,4), dim3(32,8)>>>(dec, enc, Wm, bm, wo);
    attn_kernel<<<dim3(8,16,2), dim3(32,8)>>>(wo, bo, out);
}